// round 1
// baseline (speedup 1.0000x reference)
#include <cuda_runtime.h>
#include <math.h>
#include <stdint.h>

#define N_NODES 114688
#define N_EDGES 917504
#define MAXC    256
#define BN_EPS  1e-5f
#define ONE_STEP 14
#define NGRAPH  (N_NODES / ONE_STEP)

// ---------------- scratch (static device globals; no allocation) ----------------
__device__ float  g_buf0[(size_t)N_NODES * MAXC];
__device__ float  g_buf1[(size_t)N_NODES * MAXC];
__device__ float  g_buf2[(size_t)N_NODES * MAXC];
__device__ float  g_dis[N_NODES];          // deg -> rsqrt(deg+1)
__device__ double g_sum[MAXC], g_sumsq[MAXC];
__device__ float  g_scale[MAXC], g_shift[MAXC];

// ---------------- degree / normalization ----------------
__global__ void deg_zero_kernel() {
    int i = blockIdx.x * blockDim.x + threadIdx.x;
    if (i < N_NODES) g_dis[i] = 0.f;
}
__global__ void deg_count_kernel(const int* __restrict__ ei) {
    int e = blockIdx.x * blockDim.x + threadIdx.x;
    if (e < N_EDGES) atomicAdd(&g_dis[ei[N_EDGES + e]], 1.0f);
}
__global__ void deg_rsqrt_kernel() {
    int i = blockIdx.x * blockDim.x + threadIdx.x;
    if (i < N_NODES) g_dis[i] = rsqrtf(g_dis[i] + 1.0f);
}

// ---------------- fp32 tiled GEMM:  C[N,Co] = A[N,K] @ W[K,Co] (+bias) ----------------
#define GBM 64
#define GBN 64
#define GBK 16
__global__ void gemm_kernel(const float* __restrict__ A, const float* __restrict__ W,
                            const float* __restrict__ bias, float* __restrict__ C,
                            int K, int Co) {
    __shared__ float As[GBK][GBM];
    __shared__ float Ws[GBK][GBN];
    int tx = threadIdx.x, ty = threadIdx.y;
    int tid = ty * 16 + tx;
    int row0 = blockIdx.y * GBM;
    int col0 = blockIdx.x * GBN;

    float acc[4][4];
#pragma unroll
    for (int i = 0; i < 4; i++)
#pragma unroll
        for (int j = 0; j < 4; j++) acc[i][j] = 0.f;

    for (int k0 = 0; k0 < K; k0 += GBK) {
        // load A tile 64x16 (transposed into shared)
        {
            int r = tid >> 2;
            int kq = (tid & 3) * 4;
            float4 v = *(const float4*)(A + (size_t)(row0 + r) * K + k0 + kq);
            As[kq + 0][r] = v.x; As[kq + 1][r] = v.y;
            As[kq + 2][r] = v.z; As[kq + 3][r] = v.w;
        }
        // load W tile 16x64 with column guard
        {
            int k = tid >> 4;
            int c = (tid & 15) * 4;
            int gc = col0 + c;
            float4 v;
            if (gc + 3 < Co) {
                v = *(const float4*)(W + (size_t)(k0 + k) * Co + gc);
            } else {
                v.x = (gc + 0 < Co) ? W[(size_t)(k0 + k) * Co + gc + 0] : 0.f;
                v.y = (gc + 1 < Co) ? W[(size_t)(k0 + k) * Co + gc + 1] : 0.f;
                v.z = (gc + 2 < Co) ? W[(size_t)(k0 + k) * Co + gc + 2] : 0.f;
                v.w = (gc + 3 < Co) ? W[(size_t)(k0 + k) * Co + gc + 3] : 0.f;
            }
            Ws[k][c + 0] = v.x; Ws[k][c + 1] = v.y; Ws[k][c + 2] = v.z; Ws[k][c + 3] = v.w;
        }
        __syncthreads();
#pragma unroll
        for (int k = 0; k < GBK; k++) {
            float a[4], w[4];
#pragma unroll
            for (int i = 0; i < 4; i++) a[i] = As[k][ty * 4 + i];
#pragma unroll
            for (int j = 0; j < 4; j++) w[j] = Ws[k][tx * 4 + j];
#pragma unroll
            for (int i = 0; i < 4; i++)
#pragma unroll
                for (int j = 0; j < 4; j++) acc[i][j] = fmaf(a[i], w[j], acc[i][j]);
        }
        __syncthreads();
    }
#pragma unroll
    for (int i = 0; i < 4; i++) {
        int gr = row0 + ty * 4 + i;
#pragma unroll
        for (int j = 0; j < 4; j++) {
            int gc = col0 + tx * 4 + j;
            if (gc < Co) {
                float v = acc[i][j];
                if (bias) v += bias[gc];
                C[(size_t)gr * Co + gc] = v;
            }
        }
    }
}

// ---------------- aggregation ----------------
// agg[i,:] = dis[i]^2 * z[i,:]   (self-loop term, also initializes the buffer)
__global__ void self_init_kernel(const float* __restrict__ z, float* __restrict__ agg, int C) {
    int idx = blockIdx.x * blockDim.x + threadIdx.x;
    int c4 = C >> 2;
    int total = N_NODES * c4;
    if (idx >= total) return;
    int row = idx / c4;
    float d = g_dis[row];
    float s = d * d;
    float4 v = ((const float4*)z)[idx];
    v.x *= s; v.y *= s; v.z *= s; v.w *= s;
    ((float4*)agg)[idx] = v;
}

// one warp per edge; float4 lanes over channels; red.global.add.v4.f32
__global__ void edge_agg_kernel(const int* __restrict__ ei, const float* __restrict__ z,
                                float* __restrict__ agg, int C) {
    int e = (blockIdx.x * blockDim.x + threadIdx.x) >> 5;
    int lane = threadIdx.x & 31;
    if (e >= N_EDGES) return;
    int src = ei[e];
    int dst = ei[N_EDGES + e];
    float nrm = g_dis[src] * g_dis[dst];
    const float4* zs = (const float4*)(z + (size_t)src * C);
    float4* ad = (float4*)(agg + (size_t)dst * C);
    int c4 = C >> 2;
    for (int c = lane; c < c4; c += 32) {
        float4 v = zs[c];
        v.x *= nrm; v.y *= nrm; v.z *= nrm; v.w *= nrm;
        asm volatile("red.global.add.v4.f32 [%0], {%1, %2, %3, %4};"
                     :: "l"(ad + c), "f"(v.x), "f"(v.y), "f"(v.z), "f"(v.w)
                     : "memory");
    }
}

// y = relu(agg + b)
__global__ void combine_relu_kernel(const float* __restrict__ agg, const float* __restrict__ b,
                                    float* __restrict__ y, int C) {
    int idx = blockIdx.x * blockDim.x + threadIdx.x;
    int c4 = C >> 2;
    int total = N_NODES * c4;
    if (idx >= total) return;
    int cc = idx % c4;
    float4 v = ((const float4*)agg)[idx];
    float4 bb = ((const float4*)b)[cc];
    v.x = fmaxf(v.x + bb.x, 0.f);
    v.y = fmaxf(v.y + bb.y, 0.f);
    v.z = fmaxf(v.z + bb.z, 0.f);
    v.w = fmaxf(v.w + bb.w, 0.f);
    ((float4*)y)[idx] = v;
}

// ---------------- batchnorm ----------------
__global__ void zero_stats_kernel() {
    int i = threadIdx.x;
    if (i < MAXC) { g_sum[i] = 0.0; g_sumsq[i] = 0.0; }
}

__global__ void bn_stats_kernel(const float* __restrict__ y, int C) {
    int c = threadIdx.x % C;
    int rg = threadIdx.x / C;
    int RG = 256 / C;
    double s = 0.0, q = 0.0;
    for (long long r = (long long)blockIdx.x * RG + rg; r < N_NODES;
         r += (long long)gridDim.x * RG) {
        float v = y[r * C + c];
        s += (double)v;
        q += (double)v * (double)v;
    }
    __shared__ double sh[512];
    sh[threadIdx.x] = s;
    sh[256 + threadIdx.x] = q;
    __syncthreads();
    if (rg == 0) {
        for (int g = 1; g < RG; g++) {
            s += sh[g * C + c];
            q += sh[256 + g * C + c];
        }
        atomicAdd(&g_sum[c], s);
        atomicAdd(&g_sumsq[c], q);
    }
}

__global__ void bn_finalize_kernel(const float* __restrict__ gam, const float* __restrict__ bet,
                                   int C) {
    int c = threadIdx.x;
    if (c >= C) return;
    double mean = g_sum[c] / (double)N_NODES;
    double var = g_sumsq[c] / (double)N_NODES - mean * mean;
    double sc = (double)gam[c] / sqrt(var + (double)BN_EPS);
    g_scale[c] = (float)sc;
    g_shift[c] = bet[c] - (float)(mean * sc);
}

__global__ void bn_apply_kernel(const float* __restrict__ in, float* __restrict__ out,
                                int C, int relu) {
    long long idx = (long long)blockIdx.x * blockDim.x + threadIdx.x;
    long long total = (long long)N_NODES * C;
    if (idx >= total) return;
    int c = (int)(idx % C);
    float v = fmaf(in[idx], g_scale[c], g_shift[c]);
    if (relu) v = fmaxf(v, 0.f);
    out[idx] = v;
}

// ---------------- gate layer 2: [N,16] x [16,1] + b ----------------
__global__ void gate2_kernel(const float* __restrict__ gin, const float* __restrict__ w,
                             const float* __restrict__ b, float* __restrict__ out) {
    int i = blockIdx.x * blockDim.x + threadIdx.x;
    if (i >= N_NODES) return;
    float acc = b[0];
#pragma unroll
    for (int k = 0; k < 16; k++) acc = fmaf(gin[(size_t)i * 16 + k], w[k], acc);
    out[i] = acc;
}

// ---------------- pooling + FC + softmax (one warp per graph of 14 nodes) -------
__global__ void pool_fc_kernel(const float* __restrict__ h, const float* __restrict__ g,
                               const float* __restrict__ fcW, const float* __restrict__ fcb,
                               float* __restrict__ out) {
    int warp = (blockIdx.x * blockDim.x + threadIdx.x) >> 5;
    int lane = threadIdx.x & 31;
    if (warp >= NGRAPH) return;
    int n0 = warp * ONE_STEP;
    const unsigned FULL = 0xffffffffu;

    float gv = (lane < ONE_STEP) ? g[n0 + lane] : -INFINITY;
    float m = gv;
#pragma unroll
    for (int o = 16; o; o >>= 1) m = fmaxf(m, __shfl_xor_sync(FULL, m, o));
    float ev = (lane < ONE_STEP) ? expf(gv - m) : 0.f;
    float s = ev;
#pragma unroll
    for (int o = 16; o; o >>= 1) s += __shfl_xor_sync(FULL, s, o);
    float inv = 1.0f / s;

    // lane c accumulates pooled channel c (C=32)
    float pooled = 0.f;
#pragma unroll
    for (int i = 0; i < ONE_STEP; i++) {
        float a = __shfl_sync(FULL, ev, i) * inv;
        pooled = fmaf(a, h[(size_t)(n0 + i) * 32 + lane], pooled);
    }

    float logits[10];
#pragma unroll
    for (int j = 0; j < 10; j++) {
        float p = pooled * fcW[lane * 10 + j];
#pragma unroll
        for (int o = 16; o; o >>= 1) p += __shfl_xor_sync(FULL, p, o);
        logits[j] = p + fcb[j];
    }
    if (lane == 0) {
        float mx = logits[0];
#pragma unroll
        for (int j = 1; j < 10; j++) mx = fmaxf(mx, logits[j]);
        float ss = 0.f;
        float e[10];
#pragma unroll
        for (int j = 0; j < 10; j++) { e[j] = expf(logits[j] - mx); ss += e[j]; }
        float invs = 1.0f / ss;
#pragma unroll
        for (int j = 0; j < 10; j++) out[warp * 10 + j] = e[j] * invs;
    }
}

// ---------------- host orchestration ----------------
static void run_conv_layer(const float* in, int Cin, int Cout,
                           const float* W, const float* b,
                           const float* gam, const float* bet,
                           const int* ei,
                           float* zbuf, float* abuf, float* ybuf) {
    dim3 bs(16, 16);
    dim3 gs((Cout + GBN - 1) / GBN, N_NODES / GBM);
    gemm_kernel<<<gs, bs>>>(in, W, nullptr, zbuf, Cin, Cout);

    int t4 = N_NODES * (Cout / 4);
    self_init_kernel<<<(t4 + 255) / 256, 256>>>(zbuf, abuf, Cout);
    edge_agg_kernel<<<N_EDGES / 8, 256>>>(ei, zbuf, abuf, Cout);
    combine_relu_kernel<<<(t4 + 255) / 256, 256>>>(abuf, b, ybuf, Cout);

    zero_stats_kernel<<<1, 256>>>();
    bn_stats_kernel<<<512, 256>>>(ybuf, Cout);
    bn_finalize_kernel<<<1, 256>>>(gam, bet, Cout);
    long long tot = (long long)N_NODES * Cout;
    bn_apply_kernel<<<(unsigned)((tot + 255) / 256), 256>>>(ybuf, ybuf, Cout, 0);
}

extern "C" void kernel_launch(void* const* d_in, const int* in_sizes, int n_in,
                              void* d_out, int out_size) {
    const float* x   = (const float*)d_in[0];
    const int*   ei  = (const int*)d_in[1];
    const float* W1  = (const float*)d_in[2];
    const float* b1  = (const float*)d_in[3];
    const float* bn1g = (const float*)d_in[4];
    const float* bn1b = (const float*)d_in[5];
    const float* W2  = (const float*)d_in[6];
    const float* b2  = (const float*)d_in[7];
    const float* bn2g = (const float*)d_in[8];
    const float* bn2b = (const float*)d_in[9];
    const float* W3  = (const float*)d_in[10];
    const float* b3  = (const float*)d_in[11];
    const float* bn3g = (const float*)d_in[12];
    const float* bn3b = (const float*)d_in[13];
    const float* W4  = (const float*)d_in[14];
    const float* b4  = (const float*)d_in[15];
    const float* bn4g = (const float*)d_in[16];
    const float* bn4b = (const float*)d_in[17];
    const float* gW1 = (const float*)d_in[18];
    const float* gb1 = (const float*)d_in[19];
    const float* gbn1g = (const float*)d_in[20];
    const float* gbn1b = (const float*)d_in[21];
    const float* gW2 = (const float*)d_in[22];
    const float* gb2 = (const float*)d_in[23];
    const float* gbn2g = (const float*)d_in[24];
    const float* gbn2b = (const float*)d_in[25];
    const float* fcW = (const float*)d_in[26];
    const float* fcb = (const float*)d_in[27];
    float* out = (float*)d_out;

    float *buf0, *buf1, *buf2;
    cudaGetSymbolAddress((void**)&buf0, g_buf0);
    cudaGetSymbolAddress((void**)&buf1, g_buf1);
    cudaGetSymbolAddress((void**)&buf2, g_buf2);

    // degree / rsqrt normalization
    deg_zero_kernel<<<(N_NODES + 255) / 256, 256>>>();
    deg_count_kernel<<<(N_EDGES + 255) / 256, 256>>>(ei);
    deg_rsqrt_kernel<<<(N_NODES + 255) / 256, 256>>>();

    // 4 GCN layers: in -> z(buf1) -> agg(buf2) -> y/h(buf0)
    run_conv_layer(x,    512, 128, W1, b1, bn1g, bn1b, ei, buf1, buf2, buf0);
    run_conv_layer(buf0, 128, 256, W2, b2, bn2g, bn2b, ei, buf1, buf2, buf0);
    run_conv_layer(buf0, 256,  64, W3, b3, bn3g, bn3b, ei, buf1, buf2, buf0);
    run_conv_layer(buf0,  64,  32, W4, b4, bn4g, bn4b, ei, buf1, buf2, buf0);

    // gate layer 1: [N,32] @ [32,16] + b -> BN -> relu   (in-place buf1)
    {
        dim3 bs(16, 16);
        dim3 gs(1, N_NODES / GBM);
        gemm_kernel<<<gs, bs>>>(buf0, gW1, gb1, buf1, 32, 16);
        zero_stats_kernel<<<1, 256>>>();
        bn_stats_kernel<<<512, 256>>>(buf1, 16);
        bn_finalize_kernel<<<1, 256>>>(gbn1g, gbn1b, 16);
        long long tot = (long long)N_NODES * 16;
        bn_apply_kernel<<<(unsigned)((tot + 255) / 256), 256>>>(buf1, buf1, 16, 1);
    }
    // gate layer 2: [N,16] @ [16,1] + b -> BN -> relu    (buf2 holds g[N])
    {
        gate2_kernel<<<(N_NODES + 255) / 256, 256>>>(buf1, gW2, gb2, buf2);
        zero_stats_kernel<<<1, 256>>>();
        bn_stats_kernel<<<512, 256>>>(buf2, 1);
        bn_finalize_kernel<<<1, 256>>>(gbn2g, gbn2b, 1);
        bn_apply_kernel<<<(N_NODES + 255) / 256, 256>>>(buf2, buf2, 1, 1);
    }

    // segment softmax pooling + FC + softmax
    pool_fc_kernel<<<(NGRAPH * 32 + 255) / 256, 256>>>(buf0, buf2, fcW, fcb, out);
}

// round 2
// speedup vs baseline: 2.0910x; 2.0910x over previous
#include <cuda_runtime.h>
#include <math.h>
#include <stdint.h>

#define N_NODES 114688
#define N_EDGES 917504
#define MAXC    256
#define BN_EPS  1e-5f
#define ONE_STEP 14
#define NGRAPH  (N_NODES / ONE_STEP)

// ---------------- scratch (static device globals; no allocation) ----------------
__device__ __align__(16) float  g_buf0[(size_t)N_NODES * MAXC];
__device__ __align__(16) float  g_buf1[(size_t)N_NODES * MAXC];
__device__ __align__(16) float  g_buf2[(size_t)N_NODES * MAXC];
__device__ float  g_dis[N_NODES];
__device__ double g_sum[MAXC], g_sumsq[MAXC];
__device__ __align__(16) float g_scaleA[MAXC], g_shiftA[MAXC];   // layers 1-3 (consumed immediately)
__device__ __align__(16) float g_scale4[32],  g_shift4[32];      // layer-4 BN (used by gate1 + pool)
__device__ __align__(16) float g_scaleG1[16], g_shiftG1[16];     // gate BN1
__device__ __align__(16) float g_scaleG2[4],  g_shiftG2[4];      // gate BN2 (scalar)

// ---------------- degree / normalization ----------------
__global__ void deg_zero_kernel() {
    int i = blockIdx.x * blockDim.x + threadIdx.x;
    if (i < N_NODES) g_dis[i] = 0.f;
}
__global__ void deg_count_kernel(const int* __restrict__ ei) {
    int e = blockIdx.x * blockDim.x + threadIdx.x;
    if (e < N_EDGES) atomicAdd(&g_dis[ei[N_EDGES + e]], 1.0f);
}
__global__ void deg_rsqrt_kernel() {
    int i = blockIdx.x * blockDim.x + threadIdx.x;
    if (i < N_NODES) g_dis[i] = rsqrtf(g_dis[i] + 1.0f);
}

// ---------------- high-intensity fp32 GEMM ----------------
// C[N,Co] = A'[N,K] @ W[K,Co]   where A' optionally = A*scale[k]+shift[k]
// Block tile 128 x BN_T, thread tile 8 x TN_T, BK=16, 256 threads.
// EPI==0: write z, and self_out = dis[row]^2 * z   (GCN self-loop init)
// EPI==1: write relu(z + bias)
template<int BN_T, int TN_T, int EPI, bool AFFINE>
__global__ __launch_bounds__(256, 2)
void gemm_kernel(const float* __restrict__ A, const float* __restrict__ W,
                 const float* __restrict__ bias, float* __restrict__ out,
                 float* __restrict__ self_out, int K, int Co) {
    __shared__ float As[16][128];
    __shared__ float Ws[16][BN_T];
    __shared__ float sc_sh[256], sf_sh[256];

    int tid = threadIdx.x;
    int tx = tid & 15, ty = tid >> 4;
    int row0 = blockIdx.y * 128;
    int col0 = blockIdx.x * BN_T;

    if (AFFINE) {
        for (int i = tid; i < K; i += 256) { sc_sh[i] = g_scaleA[i]; sf_sh[i] = g_shiftA[i]; }
    }

    float acc[8][TN_T];
#pragma unroll
    for (int i = 0; i < 8; i++)
#pragma unroll
        for (int j = 0; j < TN_T; j++) acc[i][j] = 0.f;

    if (AFFINE) __syncthreads();

    for (int k0 = 0; k0 < K; k0 += 16) {
        // A tile 128x16 -> transposed shared
#pragma unroll
        for (int i = 0; i < 2; i++) {
            int f = tid * 2 + i;            // 0..511
            int r = f >> 2;
            int kq = (f & 3) * 4;
            float4 v = *(const float4*)(A + (size_t)(row0 + r) * K + k0 + kq);
            if (AFFINE) {
                v.x = fmaf(v.x, sc_sh[k0 + kq + 0], sf_sh[k0 + kq + 0]);
                v.y = fmaf(v.y, sc_sh[k0 + kq + 1], sf_sh[k0 + kq + 1]);
                v.z = fmaf(v.z, sc_sh[k0 + kq + 2], sf_sh[k0 + kq + 2]);
                v.w = fmaf(v.w, sc_sh[k0 + kq + 3], sf_sh[k0 + kq + 3]);
            }
            As[kq + 0][r] = v.x; As[kq + 1][r] = v.y;
            As[kq + 2][r] = v.z; As[kq + 3][r] = v.w;
        }
        // W tile 16 x BN_T
        {
            const int NF4 = 16 * BN_T / 4;
#pragma unroll
            for (int i = 0; i < (NF4 + 255) / 256; i++) {
                int f = tid + i * 256;
                if ((NF4 % 256 == 0) || f < NF4) {
                    int k = f / (BN_T / 4);
                    int c = (f % (BN_T / 4)) * 4;
                    float4 v = *(const float4*)(W + (size_t)(k0 + k) * Co + col0 + c);
                    Ws[k][c + 0] = v.x; Ws[k][c + 1] = v.y;
                    Ws[k][c + 2] = v.z; Ws[k][c + 3] = v.w;
                }
            }
        }
        __syncthreads();
#pragma unroll
        for (int kk = 0; kk < 16; kk++) {
            float a[8], w[TN_T];
            // split-halves row fragment: conflict-free smem reads
            float4 a0 = *(const float4*)&As[kk][ty * 4];
            float4 a1 = *(const float4*)&As[kk][64 + ty * 4];
            a[0] = a0.x; a[1] = a0.y; a[2] = a0.z; a[3] = a0.w;
            a[4] = a1.x; a[5] = a1.y; a[6] = a1.z; a[7] = a1.w;
            if (TN_T == 8) {
                float4 w0 = *(const float4*)&Ws[kk][tx * 4];
                float4 w1 = *(const float4*)&Ws[kk][64 + tx * 4];
                w[0] = w0.x; w[1] = w0.y; w[2] = w0.z; w[3] = w0.w;
                w[4] = w1.x; w[5] = w1.y; w[6] = w1.z; w[7] = w1.w;
            } else if (TN_T == 4) {
                float4 w0 = *(const float4*)&Ws[kk][tx * 4];
                w[0] = w0.x; w[1] = w0.y; w[2] = w0.z; w[3] = w0.w;
            } else {
                float2 w0 = *(const float2*)&Ws[kk][tx * 2];
                w[0] = w0.x; w[1] = w0.y;
            }
#pragma unroll
            for (int i = 0; i < 8; i++)
#pragma unroll
                for (int j = 0; j < TN_T; j++) acc[i][j] = fmaf(a[i], w[j], acc[i][j]);
        }
        __syncthreads();
    }

    // epilogue
#pragma unroll
    for (int i = 0; i < 8; i++) {
        int r = row0 + ((i < 4) ? (ty * 4 + i) : (64 + ty * 4 + i - 4));
        if (EPI == 0) {
            float d = g_dis[r];
            float s = d * d;
            if (TN_T >= 4) {
#pragma unroll
                for (int jh = 0; jh < TN_T / 4; jh++) {
                    int c = col0 + ((jh == 0) ? tx * 4 : 64 + tx * 4);
                    float4 v = make_float4(acc[i][jh * 4 + 0], acc[i][jh * 4 + 1],
                                           acc[i][jh * 4 + 2], acc[i][jh * 4 + 3]);
                    *(float4*)(out + (size_t)r * Co + c) = v;
                    float4 sv = make_float4(v.x * s, v.y * s, v.z * s, v.w * s);
                    *(float4*)(self_out + (size_t)r * Co + c) = sv;
                }
            } else {
                int c = col0 + tx * 2;
                float2 v = make_float2(acc[i][0], acc[i][1]);
                *(float2*)(out + (size_t)r * Co + c) = v;
                float2 sv = make_float2(v.x * s, v.y * s);
                *(float2*)(self_out + (size_t)r * Co + c) = sv;
            }
        } else {
            if (TN_T >= 4) {
#pragma unroll
                for (int jh = 0; jh < TN_T / 4; jh++) {
                    int c = col0 + ((jh == 0) ? tx * 4 : 64 + tx * 4);
                    float4 bb = *(const float4*)(bias + c);
                    float4 v;
                    v.x = fmaxf(acc[i][jh * 4 + 0] + bb.x, 0.f);
                    v.y = fmaxf(acc[i][jh * 4 + 1] + bb.y, 0.f);
                    v.z = fmaxf(acc[i][jh * 4 + 2] + bb.z, 0.f);
                    v.w = fmaxf(acc[i][jh * 4 + 3] + bb.w, 0.f);
                    *(float4*)(out + (size_t)r * Co + c) = v;
                }
            } else {
                int c = col0 + tx * 2;
                float2 v;
                v.x = fmaxf(acc[i][0] + bias[c], 0.f);
                v.y = fmaxf(acc[i][1] + bias[c + 1], 0.f);
                *(float2*)(out + (size_t)r * Co + c) = v;
            }
        }
    }
}

// ---------------- aggregation ----------------
// self-loop init with fused BN affine: agg[i] = dis[i]^2 * (y[i]*scale + shift)
template<int C>
__global__ void self_init_affine_kernel(const float* __restrict__ y, float* __restrict__ agg) {
    const int c4n = C / 4;
    int idx = blockIdx.x * blockDim.x + threadIdx.x;
    int total = N_NODES * c4n;
    if (idx >= total) return;
    int row = idx / c4n;
    int cc = idx % c4n;
    float d = g_dis[row];
    float s = d * d;
    float4 v  = ((const float4*)y)[idx];
    float4 sc = ((const float4*)g_scaleA)[cc];
    float4 sf = ((const float4*)g_shiftA)[cc];
    float4 o;
    o.x = fmaf(v.x, sc.x, sf.x) * s;
    o.y = fmaf(v.y, sc.y, sf.y) * s;
    o.z = fmaf(v.z, sc.z, sf.z) * s;
    o.w = fmaf(v.w, sc.w, sf.w) * s;
    ((float4*)agg)[idx] = o;
}

// edge aggregation: EPW edges per warp; fused BN affine on gather if AFFINE
template<int C, bool AFFINE>
__global__ void edge_agg_kernel(const int* __restrict__ ei, const float* __restrict__ z,
                                float* __restrict__ agg) {
    const int c4n = C / 4;
    const int EPW = 32 / c4n;
    int warp = (blockIdx.x * blockDim.x + threadIdx.x) >> 5;
    int lane = threadIdx.x & 31;
    int sub = lane / c4n;
    int cc  = lane % c4n;
    long long e = (long long)warp * EPW + sub;
    if (e >= N_EDGES) return;
    int src = ei[e];
    int dst = ei[N_EDGES + e];
    float nrm = g_dis[src] * g_dis[dst];
    float4 v = *((const float4*)(z + (size_t)src * C) + cc);
    float4 o;
    if (AFFINE) {
        float4 sc = ((const float4*)g_scaleA)[cc];
        float4 sf = ((const float4*)g_shiftA)[cc];
        o.x = fmaf(v.x, sc.x, sf.x) * nrm;
        o.y = fmaf(v.y, sc.y, sf.y) * nrm;
        o.z = fmaf(v.z, sc.z, sf.z) * nrm;
        o.w = fmaf(v.w, sc.w, sf.w) * nrm;
    } else {
        o.x = v.x * nrm; o.y = v.y * nrm; o.z = v.z * nrm; o.w = v.w * nrm;
    }
    float4* ad = (float4*)(agg + (size_t)dst * C) + cc;
    asm volatile("red.global.add.v4.f32 [%0], {%1, %2, %3, %4};"
                 :: "l"(ad), "f"(o.x), "f"(o.y), "f"(o.z), "f"(o.w)
                 : "memory");
}

// ---------------- fused combine + relu + BN-stats ----------------
__global__ void zero_stats_kernel() {
    int i = threadIdx.x;
    if (i < MAXC) { g_sum[i] = 0.0; g_sumsq[i] = 0.0; }
}

// y = relu(agg + b), accumulate per-channel sum/sumsq
template<int C>
__global__ void combine_stats_kernel(const float* __restrict__ agg, const float* __restrict__ b,
                                     float* __restrict__ y) {
    const int c4n = C / 4;
    const int ROWS = 256 / c4n;
    int cc = threadIdx.x % c4n;
    int rg = threadIdx.x / c4n;
    float4 bb = ((const float4*)b)[cc];
    float s[4] = {0, 0, 0, 0}, q[4] = {0, 0, 0, 0};
    for (int r = blockIdx.x * ROWS + rg; r < N_NODES; r += gridDim.x * ROWS) {
        float4 v = *((const float4*)(agg + (size_t)r * C) + cc);
        v.x = fmaxf(v.x + bb.x, 0.f);
        v.y = fmaxf(v.y + bb.y, 0.f);
        v.z = fmaxf(v.z + bb.z, 0.f);
        v.w = fmaxf(v.w + bb.w, 0.f);
        *((float4*)(y + (size_t)r * C) + cc) = v;
        s[0] += v.x; q[0] += v.x * v.x;
        s[1] += v.y; q[1] += v.y * v.y;
        s[2] += v.z; q[2] += v.z * v.z;
        s[3] += v.w; q[3] += v.w * v.w;
    }
    __shared__ float shs[256 * 4], shq[256 * 4];
#pragma unroll
    for (int j = 0; j < 4; j++) { shs[threadIdx.x * 4 + j] = s[j]; shq[threadIdx.x * 4 + j] = q[j]; }
    __syncthreads();
    if (rg == 0) {
#pragma unroll 1
        for (int g = 1; g < ROWS; g++) {
            int base = (g * c4n + cc) * 4;
#pragma unroll
            for (int j = 0; j < 4; j++) { s[j] += shs[base + j]; q[j] += shq[base + j]; }
        }
#pragma unroll
        for (int j = 0; j < 4; j++) {
            atomicAdd(&g_sum[cc * 4 + j],   (double)s[j]);
            atomicAdd(&g_sumsq[cc * 4 + j], (double)q[j]);
        }
    }
}

// stats only (no write): for L2 (post-GEMM relu'd y) and gate1 pre-activation
template<int C>
__global__ void stats_only_kernel(const float* __restrict__ y) {
    const int c4n = C / 4;
    const int ROWS = 256 / c4n;
    int cc = threadIdx.x % c4n;
    int rg = threadIdx.x / c4n;
    float s[4] = {0, 0, 0, 0}, q[4] = {0, 0, 0, 0};
    for (int r = blockIdx.x * ROWS + rg; r < N_NODES; r += gridDim.x * ROWS) {
        float4 v = *((const float4*)(y + (size_t)r * C) + cc);
        s[0] += v.x; q[0] += v.x * v.x;
        s[1] += v.y; q[1] += v.y * v.y;
        s[2] += v.z; q[2] += v.z * v.z;
        s[3] += v.w; q[3] += v.w * v.w;
    }
    __shared__ float shs[256 * 4], shq[256 * 4];
#pragma unroll
    for (int j = 0; j < 4; j++) { shs[threadIdx.x * 4 + j] = s[j]; shq[threadIdx.x * 4 + j] = q[j]; }
    __syncthreads();
    if (rg == 0) {
#pragma unroll 1
        for (int g = 1; g < ROWS; g++) {
            int base = (g * c4n + cc) * 4;
#pragma unroll
            for (int j = 0; j < 4; j++) { s[j] += shs[base + j]; q[j] += shq[base + j]; }
        }
#pragma unroll
        for (int j = 0; j < 4; j++) {
            atomicAdd(&g_sum[cc * 4 + j],   (double)s[j]);
            atomicAdd(&g_sumsq[cc * 4 + j], (double)q[j]);
        }
    }
}

// stats for C==1
__global__ void stats_c1_kernel(const float* __restrict__ v) {
    float s = 0.f, q = 0.f;
    for (int i = blockIdx.x * 256 + threadIdx.x; i < N_NODES; i += gridDim.x * 256) {
        float x = v[i];
        s += x; q += x * x;
    }
    __shared__ float shs[256], shq[256];
    shs[threadIdx.x] = s; shq[threadIdx.x] = q;
    __syncthreads();
    for (int o = 128; o; o >>= 1) {
        if (threadIdx.x < o) { shs[threadIdx.x] += shs[threadIdx.x + o]; shq[threadIdx.x] += shq[threadIdx.x + o]; }
        __syncthreads();
    }
    if (threadIdx.x == 0) {
        atomicAdd(&g_sum[0],   (double)shs[0]);
        atomicAdd(&g_sumsq[0], (double)shq[0]);
    }
}

__global__ void bn_finalize_kernel(const float* __restrict__ gam, const float* __restrict__ bet,
                                   int C, float* __restrict__ oS, float* __restrict__ oH) {
    int c = threadIdx.x;
    if (c >= C) return;
    double mean = g_sum[c] / (double)N_NODES;
    double var = g_sumsq[c] / (double)N_NODES - mean * mean;
    double sc = (double)gam[c] / sqrt(var + (double)BN_EPS);
    oS[c] = (float)sc;
    oH[c] = bet[c] - (float)(mean * sc);
}

// ---------------- gate network ----------------
// z = (y4*scale4+shift4) @ gW1 + gb1   (one thread per row)
__global__ void gate1_kernel(const float* __restrict__ y4, const float* __restrict__ gW1,
                             const float* __restrict__ gb1, float* __restrict__ outz) {
    __shared__ float w[32 * 16];
    __shared__ float bb[16], sc[32], sf[32];
    int tid = threadIdx.x;
    for (int i = tid; i < 512; i += 256) w[i] = gW1[i];
    if (tid < 16) bb[tid] = gb1[tid];
    if (tid < 32) { sc[tid] = g_scale4[tid]; sf[tid] = g_shift4[tid]; }
    __syncthreads();
    int row = blockIdx.x * 256 + tid;
    float h[32];
#pragma unroll
    for (int k4 = 0; k4 < 8; k4++) {
        float4 v = *((const float4*)(y4 + (size_t)row * 32) + k4);
        h[k4 * 4 + 0] = fmaf(v.x, sc[k4 * 4 + 0], sf[k4 * 4 + 0]);
        h[k4 * 4 + 1] = fmaf(v.y, sc[k4 * 4 + 1], sf[k4 * 4 + 1]);
        h[k4 * 4 + 2] = fmaf(v.z, sc[k4 * 4 + 2], sf[k4 * 4 + 2]);
        h[k4 * 4 + 3] = fmaf(v.w, sc[k4 * 4 + 3], sf[k4 * 4 + 3]);
    }
    float acc[16];
#pragma unroll
    for (int j = 0; j < 16; j++) acc[j] = bb[j];
#pragma unroll
    for (int k = 0; k < 32; k++)
#pragma unroll
        for (int j = 0; j < 16; j++) acc[j] = fmaf(h[k], w[k * 16 + j], acc[j]);
#pragma unroll
    for (int j4 = 0; j4 < 4; j4++)
        *((float4*)(outz + (size_t)row * 16) + j4) =
            make_float4(acc[j4 * 4], acc[j4 * 4 + 1], acc[j4 * 4 + 2], acc[j4 * 4 + 3]);
}

// g2 = relu(z*scaleG1+shiftG1) @ gW2 + gb2
__global__ void gate2_kernel(const float* __restrict__ z, const float* __restrict__ gW2,
                             const float* __restrict__ gb2, float* __restrict__ out) {
    __shared__ float w[16], sc[16], sf[16], b0;
    int tid = threadIdx.x;
    if (tid < 16) { w[tid] = gW2[tid]; sc[tid] = g_scaleG1[tid]; sf[tid] = g_shiftG1[tid]; }
    if (tid == 0) b0 = gb2[0];
    __syncthreads();
    int row = blockIdx.x * 256 + tid;
    float acc = b0;
#pragma unroll
    for (int k4 = 0; k4 < 4; k4++) {
        float4 v = *((const float4*)(z + (size_t)row * 16) + k4);
        acc = fmaf(fmaxf(fmaf(v.x, sc[k4 * 4 + 0], sf[k4 * 4 + 0]), 0.f), w[k4 * 4 + 0], acc);
        acc = fmaf(fmaxf(fmaf(v.y, sc[k4 * 4 + 1], sf[k4 * 4 + 1]), 0.f), w[k4 * 4 + 1], acc);
        acc = fmaf(fmaxf(fmaf(v.z, sc[k4 * 4 + 2], sf[k4 * 4 + 2]), 0.f), w[k4 * 4 + 2], acc);
        acc = fmaf(fmaxf(fmaf(v.w, sc[k4 * 4 + 3], sf[k4 * 4 + 3]), 0.f), w[k4 * 4 + 3], acc);
    }
    out[row] = acc;
}

// ---------------- pooling + FC + softmax ----------------
__global__ void pool_fc_kernel(const float* __restrict__ y4, const float* __restrict__ g2,
                               const float* __restrict__ fcW, const float* __restrict__ fcb,
                               float* __restrict__ out) {
    int warp = (blockIdx.x * blockDim.x + threadIdx.x) >> 5;
    int lane = threadIdx.x & 31;
    if (warp >= NGRAPH) return;
    int n0 = warp * ONE_STEP;
    const unsigned FULL = 0xffffffffu;

    float scG = g_scaleG2[0], sfG = g_shiftG2[0];
    float gv = (lane < ONE_STEP) ? fmaxf(fmaf(g2[n0 + lane], scG, sfG), 0.f) : -INFINITY;
    float m = gv;
#pragma unroll
    for (int o = 16; o; o >>= 1) m = fmaxf(m, __shfl_xor_sync(FULL, m, o));
    float ev = (lane < ONE_STEP) ? expf(gv - m) : 0.f;
    float s = ev;
#pragma unroll
    for (int o = 16; o; o >>= 1) s += __shfl_xor_sync(FULL, s, o);
    float inv = 1.0f / s;

    float sc4 = g_scale4[lane], sf4 = g_shift4[lane];
    float pooled = 0.f;
#pragma unroll
    for (int i = 0; i < ONE_STEP; i++) {
        float a = __shfl_sync(FULL, ev, i) * inv;
        float hv = fmaf(y4[(size_t)(n0 + i) * 32 + lane], sc4, sf4);
        pooled = fmaf(a, hv, pooled);
    }

    float logits[10];
#pragma unroll
    for (int j = 0; j < 10; j++) {
        float p = pooled * fcW[lane * 10 + j];
#pragma unroll
        for (int o = 16; o; o >>= 1) p += __shfl_xor_sync(FULL, p, o);
        logits[j] = p + fcb[j];
    }
    if (lane == 0) {
        float mx = logits[0];
#pragma unroll
        for (int j = 1; j < 10; j++) mx = fmaxf(mx, logits[j]);
        float ss = 0.f;
        float e[10];
#pragma unroll
        for (int j = 0; j < 10; j++) { e[j] = expf(logits[j] - mx); ss += e[j]; }
        float invs = 1.0f / ss;
#pragma unroll
        for (int j = 0; j < 10; j++) out[warp * 10 + j] = e[j] * invs;
    }
}

// ---------------- host orchestration ----------------
extern "C" void kernel_launch(void* const* d_in, const int* in_sizes, int n_in,
                              void* d_out, int out_size) {
    const float* x    = (const float*)d_in[0];
    const int*   ei   = (const int*)d_in[1];
    const float* W1   = (const float*)d_in[2];
    const float* b1   = (const float*)d_in[3];
    const float* bn1g = (const float*)d_in[4];
    const float* bn1b = (const float*)d_in[5];
    const float* W2   = (const float*)d_in[6];
    const float* b2   = (const float*)d_in[7];
    const float* bn2g = (const float*)d_in[8];
    const float* bn2b = (const float*)d_in[9];
    const float* W3   = (const float*)d_in[10];
    const float* b3   = (const float*)d_in[11];
    const float* bn3g = (const float*)d_in[12];
    const float* bn3b = (const float*)d_in[13];
    const float* W4   = (const float*)d_in[14];
    const float* b4   = (const float*)d_in[15];
    const float* bn4g = (const float*)d_in[16];
    const float* bn4b = (const float*)d_in[17];
    const float* gW1  = (const float*)d_in[18];
    const float* gb1  = (const float*)d_in[19];
    const float* gbn1g = (const float*)d_in[20];
    const float* gbn1b = (const float*)d_in[21];
    const float* gW2  = (const float*)d_in[22];
    const float* gb2  = (const float*)d_in[23];
    const float* gbn2g = (const float*)d_in[24];
    const float* gbn2b = (const float*)d_in[25];
    const float* fcW  = (const float*)d_in[26];
    const float* fcb  = (const float*)d_in[27];
    float* out = (float*)d_out;

    float *buf0, *buf1, *buf2;
    float *scA, *shA, *sc4, *sh4, *scG1, *shG1, *scG2, *shG2;
    cudaGetSymbolAddress((void**)&buf0, g_buf0);
    cudaGetSymbolAddress((void**)&buf1, g_buf1);
    cudaGetSymbolAddress((void**)&buf2, g_buf2);
    cudaGetSymbolAddress((void**)&scA, g_scaleA);
    cudaGetSymbolAddress((void**)&shA, g_shiftA);
    cudaGetSymbolAddress((void**)&sc4, g_scale4);
    cudaGetSymbolAddress((void**)&sh4, g_shift4);
    cudaGetSymbolAddress((void**)&scG1, g_scaleG1);
    cudaGetSymbolAddress((void**)&shG1, g_shiftG1);
    cudaGetSymbolAddress((void**)&scG2, g_scaleG2);
    cudaGetSymbolAddress((void**)&shG2, g_shiftG2);

    const int GY = N_NODES / 128;  // 896

    // degree / rsqrt normalization
    deg_zero_kernel<<<(N_NODES + 255) / 256, 256>>>();
    deg_count_kernel<<<(N_EDGES + 255) / 256, 256>>>(ei);
    deg_rsqrt_kernel<<<(N_NODES + 255) / 256, 256>>>();

    // ---- Layer 1 (512 -> 128), GEMM first ----
    gemm_kernel<128, 8, 0, false><<<dim3(1, GY), 256>>>(x, W1, nullptr, buf1, buf2, 512, 128);
    edge_agg_kernel<128, false><<<N_EDGES / 8, 256>>>(ei, buf1, buf2);
    zero_stats_kernel<<<1, 256>>>();
    combine_stats_kernel<128><<<512, 256>>>(buf2, b1, buf0);
    bn_finalize_kernel<<<1, 128>>>(bn1g, bn1b, 128, scA, shA);

    // ---- Layer 2 (128 -> 256), aggregate FIRST on 128 ch (BN fused into gather) ----
    self_init_affine_kernel<128><<<(N_NODES * 32 + 255) / 256, 256>>>(buf0, buf2);
    edge_agg_kernel<128, true><<<N_EDGES / 8, 256>>>(ei, buf0, buf2);
    gemm_kernel<128, 8, 1, false><<<dim3(2, GY), 256>>>(buf2, W2, b2, buf0, nullptr, 128, 256);
    zero_stats_kernel<<<1, 256>>>();
    stats_only_kernel<256><<<512, 256>>>(buf0);
    bn_finalize_kernel<<<1, 256>>>(bn2g, bn2b, 256, scA, shA);

    // ---- Layer 3 (256 -> 64), GEMM first, BN fused into A load ----
    gemm_kernel<64, 4, 0, true><<<dim3(1, GY), 256>>>(buf0, W3, nullptr, buf1, buf2, 256, 64);
    edge_agg_kernel<64, false><<<N_EDGES / 16, 256>>>(ei, buf1, buf2);
    zero_stats_kernel<<<1, 256>>>();
    combine_stats_kernel<64><<<512, 256>>>(buf2, b3, buf0);
    bn_finalize_kernel<<<1, 64>>>(bn3g, bn3b, 64, scA, shA);

    // ---- Layer 4 (64 -> 32), GEMM first, BN fused into A load ----
    gemm_kernel<32, 2, 0, true><<<dim3(1, GY), 256>>>(buf0, W4, nullptr, buf1, buf2, 64, 32);
    edge_agg_kernel<32, false><<<N_EDGES / 32, 256>>>(ei, buf1, buf2);
    zero_stats_kernel<<<1, 256>>>();
    combine_stats_kernel<32><<<512, 256>>>(buf2, b4, buf0);
    bn_finalize_kernel<<<1, 32>>>(bn4g, bn4b, 32, sc4, sh4);

    // ---- gate layer 1: (y4 affine) @ gW1 + gb1 -> stats -> BN ----
    gate1_kernel<<<N_NODES / 256, 256>>>(buf0, gW1, gb1, buf1);
    zero_stats_kernel<<<1, 256>>>();
    stats_only_kernel<16><<<512, 256>>>(buf1);
    bn_finalize_kernel<<<1, 16>>>(gbn1g, gbn1b, 16, scG1, shG1);

    // ---- gate layer 2: relu(z affine) @ gW2 + gb2 -> stats -> BN ----
    gate2_kernel<<<N_NODES / 256, 256>>>(buf1, gW2, gb2, buf2);
    zero_stats_kernel<<<1, 256>>>();
    stats_c1_kernel<<<128, 256>>>(buf2);
    bn_finalize_kernel<<<1, 32>>>(gbn2g, gbn2b, 1, scG2, shG2);

    // ---- segment softmax pooling + FC + softmax ----
    pool_fc_kernel<<<(NGRAPH * 32 + 255) / 256, 256>>>(buf0, buf2, fcW, fcb, out);
}